// round 13
// baseline (speedup 1.0000x reference)
#include <cuda_runtime.h>
#include <cuda_fp16.h>
#include <cstdint>

#define B_  8
#define T_  512
#define C_  1024
#define NH_ 16
#define DH_ 64
#define HW_ 256

// fp16 scratch: [x:4M][src:4M][Wq:1M][Wk:1M][Wv:1M][Wp:1M] halves
#define X_OFF  0u
#define S_OFF  4194304u
#define W_OFF  8388608u
#define W_SZ   1048576u
__device__ __half g_H[12 * 1048576];
__device__ __half g_Q[B_ * T_ * C_];
__device__ __half g_K[B_ * T_ * C_];
__device__ __half g_V[B_ * T_ * C_];
__device__ __half g_Y[B_ * T_ * C_];

__device__ __forceinline__ unsigned packh2(float a, float b) {
    __half2 h = __floats2half2_rn(a, b);
    return *(unsigned*)&h;
}

__device__ __forceinline__ void mma_f16(float* c, const unsigned* a, const unsigned* b) {
    asm volatile(
        "mma.sync.aligned.m16n8k16.row.col.f32.f16.f16.f32 "
        "{%0,%1,%2,%3},{%4,%5,%6,%7},{%8,%9},{%0,%1,%2,%3};"
        : "+f"(c[0]), "+f"(c[1]), "+f"(c[2]), "+f"(c[3])
        : "r"(a[0]), "r"(a[1]), "r"(a[2]), "r"(a[3]), "r"(b[0]), "r"(b[1]));
}

__device__ __forceinline__ unsigned smaddr(const void* p) {
    unsigned a;
    asm("{ .reg .u64 t; cvta.to.shared.u64 t, %1; cvt.u32.u64 %0, t; }"
        : "=r"(a) : "l"(p));
    return a;
}
#define CP16(dst, src) \
    asm volatile("cp.async.cg.shared.global [%0], [%1], 16;" :: "r"(dst), "l"(src))
#define CP_COMMIT() asm volatile("cp.async.commit_group;" ::: "memory")
#define CP_WAIT0()  asm volatile("cp.async.wait_group 0;" ::: "memory")

__device__ __forceinline__ void ldmx4(unsigned& r0, unsigned& r1, unsigned& r2,
                                      unsigned& r3, unsigned a) {
    asm volatile("ldmatrix.sync.aligned.m8n8.x4.shared.b16 {%0,%1,%2,%3}, [%4];"
                 : "=r"(r0), "=r"(r1), "=r"(r2), "=r"(r3) : "r"(a));
}
__device__ __forceinline__ void ldmx2t(unsigned& r0, unsigned& r1, unsigned a) {
    asm volatile("ldmatrix.sync.aligned.m8n8.x2.trans.shared.b16 {%0,%1}, [%2];"
                 : "=r"(r0), "=r"(r1) : "r"(a));
}

// ---------------------------------------------------------------------------
// Prep: fp32 -> fp16 once.
// ---------------------------------------------------------------------------
__global__ __launch_bounds__(256) void prep_fp16(
    const float4* __restrict__ x, const float4* __restrict__ src,
    const float4* __restrict__ wq, const float4* __restrict__ wk,
    const float4* __restrict__ wv, const float4* __restrict__ wp)
{
    unsigned i = blockIdx.x * 256 + threadIdx.x;
    const float4* s; unsigned off;
    if      (i < 1048576u) { s = x;   off = i; }
    else if (i < 2097152u) { s = src; off = i - 1048576u; }
    else if (i < 2359296u) { s = wq;  off = i - 2097152u; }
    else if (i < 2621440u) { s = wk;  off = i - 2359296u; }
    else if (i < 2883584u) { s = wv;  off = i - 2621440u; }
    else                   { s = wp;  off = i - 2883584u; }
    float4 v = s[off];
    uint2 u = {packh2(v.x, v.y), packh2(v.z, v.w)};
    ((uint2*)g_H)[i] = u;
}

// ---------------------------------------------------------------------------
// fp16 GEMM: C[m,n] = sum_k A[m,k]*W[n,k] + bias[n].
// 128x64 tile, BK=64, 2-stage cp.async, ldmatrix, 3 CTAs/SM.
// smem: A[2][128][72]h (18432B/stage) | B[2][64][72]h (9216B/stage) = 55296 B
// Warps 4x2, warp tile 32x32.
// ---------------------------------------------------------------------------
#define ABUF 18432u
#define BBUF 9216u
#define GEMM_SMEM (2 * 18432 + 2 * 9216)

template <bool H16OUT>
__device__ __forceinline__ void gemm_body_h(
    const __half* __restrict__ A, const __half* __restrict__ W,
    const float* __restrict__ bias, void* __restrict__ Cmat,
    int N, int K, int bx, int by)
{
    extern __shared__ char smc[];
    const unsigned smA = smaddr(smc);
    const unsigned smB = smA + 2 * ABUF;

    const int tid = threadIdx.x, lane = tid & 31, warp = tid >> 5;
    const int wm0 = (warp >> 1) * 32, wn0 = (warp & 1) * 32;
    const int g = lane >> 2, tg = lane & 3;
    const int m0 = by * 128, n0 = bx * 64;

    float acc[2][4][4] = {};

    const int alrow = tid >> 1, alch4 = (tid & 1) * 4;   // A staging
    const int blrow = tid >> 2, blch = tid & 3;          // B staging

    auto fill = [&](int buf, int kt) {
#pragma unroll
        for (int cc = 0; cc < 4; cc++) {
            int ch = alch4 + cc;
            CP16(smA + (unsigned)(buf * (int)ABUF + alrow * 144 + ch * 16),
                 A + (size_t)(m0 + alrow) * K + kt * 64 + ch * 8);
        }
#pragma unroll
        for (int cc = 0; cc < 2; cc++) {
            int ch = blch + cc * 4;
            CP16(smB + (unsigned)(buf * (int)BBUF + blrow * 144 + ch * 16),
                 W + (size_t)(n0 + blrow) * K + kt * 64 + ch * 8);
        }
    };

    fill(0, 0);
    CP_COMMIT();
    CP_WAIT0();
    __syncthreads();

    // fragment ldmatrix addressing
    const int arow = lane & 15, ak = (lane >> 4) * 8;    // A: x4
    const int brow = (lane & 7) + (lane >> 4) * 8;       // B: x4 (2 ni per)
    const int bk = ((lane >> 3) & 1) * 8;

    int cur = 0;
    const int NT = K / 64;   // 16
    for (int kt = 0; kt < NT; kt++) {
        const bool has_next = (kt + 1 < NT);
        if (has_next) { fill(cur ^ 1, kt + 1); CP_COMMIT(); }
        const unsigned ab = smA + (unsigned)(cur * (int)ABUF);
        const unsigned bb = smB + (unsigned)(cur * (int)BBUF);
#pragma unroll
        for (int ks = 0; ks < 4; ks++) {
            const int c = ks * 16;   // halves
            unsigned af[2][4], bf[4][2];
#pragma unroll
            for (int mi = 0; mi < 2; mi++)
                ldmx4(af[mi][0], af[mi][1], af[mi][2], af[mi][3],
                      ab + (unsigned)((wm0 + mi * 16 + arow) * 144 + (c + ak) * 2));
#pragma unroll
            for (int np = 0; np < 2; np++)
                ldmx4(bf[2 * np][0], bf[2 * np][1], bf[2 * np + 1][0], bf[2 * np + 1][1],
                      bb + (unsigned)((wn0 + np * 16 + brow) * 144 + (c + bk) * 2));
#pragma unroll
            for (int mi = 0; mi < 2; mi++)
#pragma unroll
                for (int ni = 0; ni < 4; ni++)
                    mma_f16(acc[mi][ni], af[mi], bf[ni]);
        }
        if (has_next) {
            CP_WAIT0();
            __syncthreads();
        }
        cur ^= 1;
    }

#pragma unroll
    for (int mi = 0; mi < 2; mi++) {
#pragma unroll
        for (int ni = 0; ni < 4; ni++) {
            int row = m0 + wm0 + mi * 16 + g;
            int col = n0 + wn0 + ni * 8 + 2 * tg;
            float b0 = bias[col], b1 = bias[col + 1];
            if (H16OUT) {
                unsigned* Cu = (unsigned*)Cmat;
                Cu[((size_t)row * N + col) >> 1] =
                    packh2(acc[mi][ni][0] + b0, acc[mi][ni][1] + b1);
                Cu[((size_t)(row + 8) * N + col) >> 1] =
                    packh2(acc[mi][ni][2] + b0, acc[mi][ni][3] + b1);
            } else {
                float* Cf = (float*)Cmat;
                float2 o0 = {acc[mi][ni][0] + b0, acc[mi][ni][1] + b1};
                float2 o1 = {acc[mi][ni][2] + b0, acc[mi][ni][3] + b1};
                *(float2*)&Cf[(size_t)row * N + col] = o0;
                *(float2*)&Cf[(size_t)(row + 8) * N + col] = o1;
            }
        }
    }
}

__global__ __launch_bounds__(256, 3) void gemm_qkv(
    const float* __restrict__ bq, const float* __restrict__ bk,
    const float* __restrict__ bv)
{
    const int z = blockIdx.z;
    const __half* A = g_H + (z == 0 ? X_OFF : S_OFF);
    const __half* W = g_H + W_OFF + (unsigned)z * W_SZ;
    const float* bias = (z == 0) ? bq : (z == 1) ? bk : bv;
    __half* out = (z == 0) ? g_Q : (z == 1) ? g_K : g_V;
    gemm_body_h<true>(A, W, bias, out, C_, C_, blockIdx.x, blockIdx.y);
}

__global__ __launch_bounds__(256, 3) void gemm_out(
    const float* __restrict__ bias, float* __restrict__ Cmat)
{
    gemm_body_h<false>(g_Y, g_H + W_OFF + 3u * W_SZ, bias, Cmat,
                       C_, C_, blockIdx.x, blockIdx.y);
}

// ---------------------------------------------------------------------------
// Fused attention fp16 (unchanged). Per CTA: 32 q x 512 k.
// smem: Ss[32][516] f32 | Qs[32][72] h | KV[2][64][72] h
// ---------------------------------------------------------------------------
#define SS_PAD 516
#define ATTN_SMEM (32 * SS_PAD * 4 + 32 * 72 * 2 + 2 * 64 * 72 * 2)

__global__ __launch_bounds__(256, 2) void attn_fused(const float* __restrict__ fmap,
                                                     const float* __restrict__ bmap)
{
    extern __shared__ char smraw[];
    float (*Ss)[SS_PAD] = (float (*)[SS_PAD])smraw;
    char* qbase = smraw + 32 * SS_PAD * 4;
    char* kvbase = qbase + 32 * 72 * 2;
    const unsigned* Qw = (const unsigned*)qbase;
    const unsigned* KVw = (const unsigned*)kvbase;
    const unsigned qsm = smaddr(qbase);
    const unsigned kvsm = smaddr(kvbase);

    const int bh = blockIdx.y, b = bh >> 4, h = bh & 15;
    const int mt = blockIdx.x * 32;
    const __half* Qp = g_Q + (size_t)b * T_ * C_ + h * DH_;
    const __half* Kp = g_K + (size_t)b * T_ * C_ + h * DH_;
    const __half* Vp = g_V + (size_t)b * T_ * C_ + h * DH_;
    const int tid = threadIdx.x, lane = tid & 31, warp = tid >> 5;
    const int g = lane >> 2, tg = lane & 3;

    auto fill_kv = [&](int buf, const __half* src, int tok0) {
        int row = tid >> 2;
#pragma unroll
        for (int cc = 0; cc < 2; cc++) {
            int ch = (tid & 3) + cc * 4;
            CP16(kvsm + (unsigned)(buf * 9216 + row * 144 + ch * 16),
                 src + (size_t)(tok0 + row) * C_ + ch * 8);
        }
    };

    {
        int row = tid >> 3, ch = tid & 7;
        CP16(qsm + (unsigned)(row * 144 + ch * 16),
             Qp + (size_t)(mt + row) * C_ + ch * 8);
    }
    fill_kv(0, Kp, 0);
    CP_COMMIT();
    CP_WAIT0();
    __syncthreads();

    // Phase 1: scores
    {
        const int wm0 = (warp >> 2) * 16, wn0 = (warp & 3) * 16;
        for (int ci = 0; ci < 8; ci++) {
            const int nt = ci * 64;
            const bool has_next = (ci < 7);
            if (has_next) { fill_kv((ci + 1) & 1, Kp, nt + 64); CP_COMMIT(); }

            float acc[2][4] = {};
            const unsigned* Kc = KVw + (ci & 1) * 2304;
#pragma unroll
            for (int ks = 0; ks < 4; ks++) {
                const int c = ks * 8;
                unsigned af[4], bf[2][2];
                af[0] = Qw[(wm0 + g) * 36 + c + tg];
                af[1] = Qw[(wm0 + g + 8) * 36 + c + tg];
                af[2] = Qw[(wm0 + g) * 36 + c + tg + 4];
                af[3] = Qw[(wm0 + g + 8) * 36 + c + tg + 4];
#pragma unroll
                for (int ni = 0; ni < 2; ni++) {
                    int n = wn0 + ni * 8 + g;
                    bf[ni][0] = Kc[n * 36 + c + tg];
                    bf[ni][1] = Kc[n * 36 + c + tg + 4];
                }
#pragma unroll
                for (int ni = 0; ni < 2; ni++)
                    mma_f16(acc[ni], af, bf[ni]);
            }

#pragma unroll
            for (int ni = 0; ni < 2; ni++) {
                int kg = nt + wn0 + ni * 8 + 2 * tg;
#pragma unroll
                for (int half = 0; half < 2; half++) {
                    int qlo = wm0 + g + half * 8;
                    int qg = mt + qlo;
                    float v0 = acc[ni][half * 2 + 0] * 0.125f;
                    float v1 = acc[ni][half * 2 + 1] * 0.125f;
                    if (qg < HW_) {
                        if (kg < HW_)
                            v0 *= fmap[((size_t)b * HW_ + qg) * HW_ + kg] *
                                  bmap[((size_t)b * HW_ + kg) * HW_ + qg];
                        if (kg + 1 < HW_)
                            v1 *= fmap[((size_t)b * HW_ + qg) * HW_ + kg + 1] *
                                  bmap[((size_t)b * HW_ + kg + 1) * HW_ + qg];
                    }
                    Ss[qlo][kg] = v0;
                    Ss[qlo][kg + 1] = v1;
                }
            }

            if (has_next) {
                CP_WAIT0();
                __syncthreads();
            }
        }
    }
    __syncthreads();

    // Phase 2: softmax -> fp16 pairs overlaid on Ss
    fill_kv(0, Vp, 0);
    CP_COMMIT();
    {
        int row = warp * 4;
#pragma unroll 1
        for (int r = 0; r < 4; r++, row++) {
            float v[16];
            float m = -1e30f;
#pragma unroll
            for (int j = 0; j < 8; j++) {
                float2 p = *(float2*)&Ss[row][2 * lane + 64 * j];
                v[2 * j] = p.x; v[2 * j + 1] = p.y;
                m = fmaxf(m, fmaxf(p.x, p.y));
            }
#pragma unroll
            for (int o = 16; o > 0; o >>= 1)
                m = fmaxf(m, __shfl_xor_sync(0xffffffffu, m, o));
            float s = 0.f;
#pragma unroll
            for (int j = 0; j < 16; j++) {
                v[j] = __expf(v[j] - m);
                s += v[j];
            }
#pragma unroll
            for (int o = 16; o > 0; o >>= 1)
                s += __shfl_xor_sync(0xffffffffu, s, o);
            float inv = 1.0f / s;
            __syncwarp();
#pragma unroll
            for (int j = 0; j < 8; j++)
                ((unsigned*)&Ss[row][0])[lane + 32 * j] =
                    packh2(v[2 * j] * inv, v[2 * j + 1] * inv);
        }
    }
    CP_WAIT0();
    __syncthreads();

    // Phase 3: O = P V
    {
        const int wm0 = (warp >> 2) * 16, wn0 = (warp & 3) * 16;
        float acc[2][4] = {};
        for (int ci = 0; ci < 8; ci++) {
            const int nt = ci * 64;
            const bool has_next = (ci < 7);
            if (has_next) { fill_kv((ci + 1) & 1, Vp, nt + 64); CP_COMMIT(); }

            const unsigned vb = kvsm + (unsigned)((ci & 1) * 9216);
#pragma unroll
            for (int ks = 0; ks < 4; ks++) {
                const int c = 16 * ks;
                unsigned af[4];
                const unsigned* P0 = (const unsigned*)&Ss[wm0 + g][0];
                const unsigned* P1 = (const unsigned*)&Ss[wm0 + g + 8][0];
                af[0] = P0[nt / 2 + 8 * ks + tg];
                af[1] = P1[nt / 2 + 8 * ks + tg];
                af[2] = P0[nt / 2 + 8 * ks + tg + 4];
                af[3] = P1[nt / 2 + 8 * ks + tg + 4];
#pragma unroll
                for (int ni = 0; ni < 2; ni++) {
                    int dbase = wn0 + ni * 8;
                    unsigned addr = vb + (unsigned)((c + (lane & 15)) * 144 + dbase * 2);
                    unsigned bf[2];
                    ldmx2t(bf[0], bf[1], addr);
                    mma_f16(acc[ni], af, bf);
                }
            }
            if (has_next) {
                CP_WAIT0();
                __syncthreads();
            }
        }

#pragma unroll
        for (int ni = 0; ni < 2; ni++) {
            int qg = mt + wm0 + g;
            int d = wn0 + ni * 8 + 2 * tg;
            unsigned* yp = (unsigned*)g_Y;
            yp[((size_t)(b * T_ + qg) * C_ + h * DH_ + d) >> 1] =
                packh2(acc[ni][0], acc[ni][1]);
            yp[((size_t)(b * T_ + qg + 8) * C_ + h * DH_ + d) >> 1] =
                packh2(acc[ni][2], acc[ni][3]);
        }
    }
}

// ---------------------------------------------------------------------------
extern "C" void kernel_launch(void* const* d_in, const int* in_sizes, int n_in,
                              void* d_out, int out_size)
{
    const float* x    = (const float*)d_in[0];
    const float* src  = (const float*)d_in[1];
    const float* fmap = (const float*)d_in[2];
    const float* bmap = (const float*)d_in[3];
    const float* Wq   = (const float*)d_in[4];
    const float* bq   = (const float*)d_in[5];
    const float* Wk   = (const float*)d_in[6];
    const float* bk   = (const float*)d_in[7];
    const float* Wv   = (const float*)d_in[8];
    const float* bv   = (const float*)d_in[9];
    const float* Wp   = (const float*)d_in[10];
    const float* bp   = (const float*)d_in[11];
    float* out = (float*)d_out;

    cudaFuncSetAttribute(gemm_qkv, cudaFuncAttributeMaxDynamicSharedMemorySize,
                         GEMM_SMEM);
    cudaFuncSetAttribute(gemm_out, cudaFuncAttributeMaxDynamicSharedMemorySize,
                         GEMM_SMEM);
    cudaFuncSetAttribute(attn_fused, cudaFuncAttributeMaxDynamicSharedMemorySize,
                         ATTN_SMEM);

    prep_fp16<<<12288, 256>>>((const float4*)x, (const float4*)src,
                              (const float4*)Wq, (const float4*)Wk,
                              (const float4*)Wv, (const float4*)Wp);

    const int M = B_ * T_;                  // 4096
    dim3 gQKV(C_ / 64, M / 128, 3);         // 16 x 32 x 3 = 1536 CTAs
    gemm_qkv<<<gQKV, 256, GEMM_SMEM>>>(bq, bk, bv);

    dim3 gAttn(T_ / 32, B_ * NH_);          // 16 x 128
    attn_fused<<<gAttn, 256, ATTN_SMEM>>>(fmap, bmap);

    dim3 gProj(C_ / 64, M / 128);           // 16 x 32 = 512 CTAs
    gemm_out<<<gProj, 256, GEMM_SMEM>>>(bp, out);
}

// round 15
// speedup vs baseline: 1.0951x; 1.0951x over previous
#include <cuda_runtime.h>
#include <cuda_fp16.h>
#include <cstdint>

#define B_  8
#define T_  512
#define C_  1024
#define NH_ 16
#define DH_ 64
#define HW_ 256

// fp16 scratch: [x:4M][src:4M][Wq:1M][Wk:1M][Wv:1M][Wp:1M] halves
#define X_OFF  0u
#define S_OFF  4194304u
#define W_OFF  8388608u
#define W_SZ   1048576u
__device__ __half g_H[12 * 1048576];
__device__ __half g_Q[B_ * T_ * C_];   // pre-scaled by 0.125
__device__ __half g_K[B_ * T_ * C_];
__device__ __half g_V[B_ * T_ * C_];
__device__ __half g_Y[B_ * T_ * C_];
__device__ float  g_M[B_ * HW_ * HW_]; // fmap[b,q,k]*bmap[b,k,q]

__device__ __forceinline__ unsigned packh2(float a, float b) {
    __half2 h = __floats2half2_rn(a, b);
    return *(unsigned*)&h;
}

__device__ __forceinline__ void mma_f16(float* c, const unsigned* a, const unsigned* b) {
    asm volatile(
        "mma.sync.aligned.m16n8k16.row.col.f32.f16.f16.f32 "
        "{%0,%1,%2,%3},{%4,%5,%6,%7},{%8,%9},{%0,%1,%2,%3};"
        : "+f"(c[0]), "+f"(c[1]), "+f"(c[2]), "+f"(c[3])
        : "r"(a[0]), "r"(a[1]), "r"(a[2]), "r"(a[3]), "r"(b[0]), "r"(b[1]));
}

__device__ __forceinline__ unsigned smaddr(const void* p) {
    unsigned a;
    asm("{ .reg .u64 t; cvta.to.shared.u64 t, %1; cvt.u32.u64 %0, t; }"
        : "=r"(a) : "l"(p));
    return a;
}
#define CP16(dst, src) \
    asm volatile("cp.async.cg.shared.global [%0], [%1], 16;" :: "r"(dst), "l"(src))
#define CP_COMMIT() asm volatile("cp.async.commit_group;" ::: "memory")
#define CP_WAIT0()  asm volatile("cp.async.wait_group 0;" ::: "memory")

__device__ __forceinline__ void ldmx4(unsigned& r0, unsigned& r1, unsigned& r2,
                                      unsigned& r3, unsigned a) {
    asm volatile("ldmatrix.sync.aligned.m8n8.x4.shared.b16 {%0,%1,%2,%3}, [%4];"
                 : "=r"(r0), "=r"(r1), "=r"(r2), "=r"(r3) : "r"(a));
}
__device__ __forceinline__ void ldmx2t(unsigned& r0, unsigned& r1, unsigned a) {
    asm volatile("ldmatrix.sync.aligned.m8n8.x2.trans.shared.b16 {%0,%1}, [%2];"
                 : "=r"(r0), "=r"(r1) : "r"(a));
}

// ---------------------------------------------------------------------------
// Prep 1: fp32 -> fp16 once.
// ---------------------------------------------------------------------------
__global__ __launch_bounds__(256) void prep_fp16(
    const float4* __restrict__ x, const float4* __restrict__ src,
    const float4* __restrict__ wq, const float4* __restrict__ wk,
    const float4* __restrict__ wv, const float4* __restrict__ wp)
{
    unsigned i = blockIdx.x * 256 + threadIdx.x;
    const float4* s; unsigned off;
    if      (i < 1048576u) { s = x;   off = i; }
    else if (i < 2097152u) { s = src; off = i - 1048576u; }
    else if (i < 2359296u) { s = wq;  off = i - 2097152u; }
    else if (i < 2621440u) { s = wk;  off = i - 2359296u; }
    else if (i < 2883584u) { s = wv;  off = i - 2621440u; }
    else                   { s = wp;  off = i - 2883584u; }
    float4 v = s[off];
    uint2 u = {packh2(v.x, v.y), packh2(v.z, v.w)};
    ((uint2*)g_H)[i] = u;
}

// ---------------------------------------------------------------------------
// Prep 2: M[b][q][k] = fmap[b,q,k] * bmap[b,k,q]  (coalesced transpose)
// 32x32 tiles; grid (8,8,B), 256 threads.
// ---------------------------------------------------------------------------
__global__ __launch_bounds__(256) void prep_mask(
    const float* __restrict__ fmap, const float* __restrict__ bmap)
{
    __shared__ float bs[32][33];
    const int tid = threadIdx.x;
    const int b = blockIdx.z, q0 = blockIdx.y * 32, k0 = blockIdx.x * 32;
    const int r8 = tid >> 5, c = tid & 31;
#pragma unroll
    for (int it = 0; it < 4; it++) {
        int kr = r8 + it * 8;
        bs[kr][c] = bmap[((size_t)b * HW_ + k0 + kr) * HW_ + q0 + c];
    }
    __syncthreads();
#pragma unroll
    for (int it = 0; it < 4; it++) {
        int qr = r8 + it * 8;
        size_t idx = ((size_t)b * HW_ + q0 + qr) * HW_ + k0 + c;
        g_M[idx] = fmap[idx] * bs[c][qr];
    }
}

// ---------------------------------------------------------------------------
// fp16 GEMM (R11 config): C[m,n] = (sum_k A[m,k]*W[n,k] + bias[n]) * scale.
// 128x128 tile, BK=64, 2-stage cp.async, ldmatrix fragments, 2 CTAs/SM.
// smem: A[2][128][72]h | B[2][128][72]h = 73728 B. Row stride 144 B.
// ---------------------------------------------------------------------------
#define ABUF 18432u
#define GEMM_SMEM 73728

template <bool H16OUT>
__device__ __forceinline__ void gemm_body_h(
    const __half* __restrict__ A, const __half* __restrict__ W,
    const float* __restrict__ bias, void* __restrict__ Cmat,
    int N, int K, int bx, int by, float scale)
{
    extern __shared__ char smc[];
    const unsigned smA = smaddr(smc);
    const unsigned smB = smA + 2 * ABUF;

    const int tid = threadIdx.x, lane = tid & 31, warp = tid >> 5;
    const int wm0 = (warp >> 2) * 64, wn0 = (warp & 3) * 32;
    const int g = lane >> 2, tg = lane & 3;
    const int m0 = by * 128, n0 = bx * 128;
    const int lrow = tid >> 1, lch4 = (tid & 1) * 4;

    float acc[4][4][4] = {};

    auto fill = [&](int buf, int kt) {
#pragma unroll
        for (int cc = 0; cc < 4; cc++) {
            int ch = lch4 + cc;
            unsigned d = (unsigned)(buf * (int)ABUF + lrow * 144 + ch * 16);
            CP16(smA + d, A + (size_t)(m0 + lrow) * K + kt * 64 + ch * 8);
            CP16(smB + d, W + (size_t)(n0 + lrow) * K + kt * 64 + ch * 8);
        }
    };

    fill(0, 0);
    CP_COMMIT();
    CP_WAIT0();
    __syncthreads();

    const int arow = lane & 15, ak = (lane >> 4) * 8;
    const int brow = (lane & 7) + (lane >> 4) * 8;
    const int bk = ((lane >> 3) & 1) * 8;

    int cur = 0;
    const int NT = K / 64;
    for (int kt = 0; kt < NT; kt++) {
        const bool has_next = (kt + 1 < NT);
        if (has_next) { fill(cur ^ 1, kt + 1); CP_COMMIT(); }
        const unsigned ab = smA + (unsigned)(cur * (int)ABUF);
        const unsigned bb = smB + (unsigned)(cur * (int)ABUF);
#pragma unroll
        for (int ks = 0; ks < 4; ks++) {
            const int c = ks * 16;
            unsigned af[4][4], bf[4][2];
#pragma unroll
            for (int mi = 0; mi < 4; mi++)
                ldmx4(af[mi][0], af[mi][1], af[mi][2], af[mi][3],
                      ab + (unsigned)((wm0 + mi * 16 + arow) * 144 + (c + ak) * 2));
#pragma unroll
            for (int np = 0; np < 2; np++)
                ldmx4(bf[2 * np][0], bf[2 * np][1], bf[2 * np + 1][0], bf[2 * np + 1][1],
                      bb + (unsigned)((wn0 + np * 16 + brow) * 144 + (c + bk) * 2));
#pragma unroll
            for (int mi = 0; mi < 4; mi++)
#pragma unroll
                for (int ni = 0; ni < 4; ni++)
                    mma_f16(acc[mi][ni], af[mi], bf[ni]);
        }
        if (has_next) {
            CP_WAIT0();
            __syncthreads();
        }
        cur ^= 1;
    }

#pragma unroll
    for (int mi = 0; mi < 4; mi++) {
#pragma unroll
        for (int ni = 0; ni < 4; ni++) {
            int row = m0 + wm0 + mi * 16 + g;
            int col = n0 + wn0 + ni * 8 + 2 * tg;
            float b0 = bias[col], b1 = bias[col + 1];
            if (H16OUT) {
                unsigned* Cu = (unsigned*)Cmat;
                Cu[((size_t)row * N + col) >> 1] =
                    packh2((acc[mi][ni][0] + b0) * scale, (acc[mi][ni][1] + b1) * scale);
                Cu[((size_t)(row + 8) * N + col) >> 1] =
                    packh2((acc[mi][ni][2] + b0) * scale, (acc[mi][ni][3] + b1) * scale);
            } else {
                float* Cf = (float*)Cmat;
                float2 o0 = {acc[mi][ni][0] + b0, acc[mi][ni][1] + b1};
                float2 o1 = {acc[mi][ni][2] + b0, acc[mi][ni][3] + b1};
                *(float2*)&Cf[(size_t)row * N + col] = o0;
                *(float2*)&Cf[(size_t)(row + 8) * N + col] = o1;
            }
        }
    }
}

__global__ __launch_bounds__(256, 2) void gemm_qkv(
    const float* __restrict__ bq, const float* __restrict__ bk,
    const float* __restrict__ bv)
{
    const int z = blockIdx.z;
    const __half* A = g_H + (z == 0 ? X_OFF : S_OFF);
    const __half* W = g_H + W_OFF + (unsigned)z * W_SZ;
    const float* bias = (z == 0) ? bq : (z == 1) ? bk : bv;
    __half* out = (z == 0) ? g_Q : (z == 1) ? g_K : g_V;
    float scale = (z == 0) ? 0.125f : 1.0f;   // fold 1/sqrt(dh) into Q (2^-3: exact)
    gemm_body_h<true>(A, W, bias, out, C_, C_, blockIdx.x, blockIdx.y, scale);
}

__global__ __launch_bounds__(256, 2) void gemm_out(
    const float* __restrict__ bias, float* __restrict__ Cmat)
{
    gemm_body_h<false>(g_Y, g_H + W_OFF + 3u * W_SZ, bias, Cmat,
                       C_, C_, blockIdx.x, blockIdx.y, 1.0f);
}

// ---------------------------------------------------------------------------
// Fused attention fp16. Per CTA: 32 q x 512 k. Mask from precomputed g_M.
// smem: Ss[32][516] f32 | Qs[32][72] h | KV[2][64][72] h
// ---------------------------------------------------------------------------
#define SS_PAD 516
#define ATTN_SMEM (32 * SS_PAD * 4 + 32 * 72 * 2 + 2 * 64 * 72 * 2)

__global__ __launch_bounds__(256, 2) void attn_fused()
{
    extern __shared__ char smraw[];
    float (*Ss)[SS_PAD] = (float (*)[SS_PAD])smraw;
    char* qbase = smraw + 32 * SS_PAD * 4;
    char* kvbase = qbase + 32 * 72 * 2;
    const unsigned* Qw = (const unsigned*)qbase;
    const unsigned* KVw = (const unsigned*)kvbase;
    const unsigned qsm = smaddr(qbase);
    const unsigned kvsm = smaddr(kvbase);

    const int bh = blockIdx.y, b = bh >> 4, h = bh & 15;
    const int mt = blockIdx.x * 32;
    const __half* Qp = g_Q + (size_t)b * T_ * C_ + h * DH_;
    const __half* Kp = g_K + (size_t)b * T_ * C_ + h * DH_;
    const __half* Vp = g_V + (size_t)b * T_ * C_ + h * DH_;
    const float* Mb = g_M + (size_t)b * HW_ * HW_;
    const int tid = threadIdx.x, lane = tid & 31, warp = tid >> 5;
    const int g = lane >> 2, tg = lane & 3;

    auto fill_kv = [&](int buf, const __half* src, int tok0) {
        int row = tid >> 2;
#pragma unroll
        for (int cc = 0; cc < 2; cc++) {
            int ch = (tid & 3) + cc * 4;
            CP16(kvsm + (unsigned)(buf * 9216 + row * 144 + ch * 16),
                 src + (size_t)(tok0 + row) * C_ + ch * 8);
        }
    };

    {
        int row = tid >> 3, ch = tid & 7;
        CP16(qsm + (unsigned)(row * 144 + ch * 16),
             Qp + (size_t)(mt + row) * C_ + ch * 8);
    }
    fill_kv(0, Kp, 0);
    CP_COMMIT();
    CP_WAIT0();
    __syncthreads();

    // Phase 1: scores (Q pre-scaled by 0.125)
    {
        const int wm0 = (warp >> 2) * 16, wn0 = (warp & 3) * 16;
        for (int ci = 0; ci < 8; ci++) {
            const int nt = ci * 64;
            const bool has_next = (ci < 7);
            if (has_next) { fill_kv((ci + 1) & 1, Kp, nt + 64); CP_COMMIT(); }

            float acc[2][4] = {};
            const unsigned* Kc = KVw + (ci & 1) * 2304;
#pragma unroll
            for (int ks = 0; ks < 4; ks++) {
                const int c = ks * 8;
                unsigned af[4], bf[2][2];
                af[0] = Qw[(wm0 + g) * 36 + c + tg];
                af[1] = Qw[(wm0 + g + 8) * 36 + c + tg];
                af[2] = Qw[(wm0 + g) * 36 + c + tg + 4];
                af[3] = Qw[(wm0 + g + 8) * 36 + c + tg + 4];
#pragma unroll
                for (int ni = 0; ni < 2; ni++) {
                    int n = wn0 + ni * 8 + g;
                    bf[ni][0] = Kc[n * 36 + c + tg];
                    bf[ni][1] = Kc[n * 36 + c + tg + 4];
                }
#pragma unroll
                for (int ni = 0; ni < 2; ni++)
                    mma_f16(acc[ni], af, bf[ni]);
            }

#pragma unroll
            for (int ni = 0; ni < 2; ni++) {
                int kg = nt + wn0 + ni * 8 + 2 * tg;
#pragma unroll
                for (int half = 0; half < 2; half++) {
                    int qlo = wm0 + g + half * 8;
                    int qg = mt + qlo;
                    float v0 = acc[ni][half * 2 + 0];
                    float v1 = acc[ni][half * 2 + 1];
                    if (qg < HW_ && kg < HW_) {   // kg even, HW even -> kg+1 < HW too
                        float2 mm = *(const float2*)&Mb[(size_t)qg * HW_ + kg];
                        v0 *= mm.x;
                        v1 *= mm.y;
                    }
                    Ss[qlo][kg] = v0;
                    Ss[qlo][kg + 1] = v1;
                }
            }

            if (has_next) {
                CP_WAIT0();
                __syncthreads();
            }
        }
    }
    __syncthreads();

    // Phase 2: softmax -> fp16 pairs overlaid on Ss
    fill_kv(0, Vp, 0);
    CP_COMMIT();
    {
        int row = warp * 4;
#pragma unroll 1
        for (int r = 0; r < 4; r++, row++) {
            float v[16];
            float m = -1e30f;
#pragma unroll
            for (int j = 0; j < 8; j++) {
                float2 p = *(float2*)&Ss[row][2 * lane + 64 * j];
                v[2 * j] = p.x; v[2 * j + 1] = p.y;
                m = fmaxf(m, fmaxf(p.x, p.y));
            }
#pragma unroll
            for (int o = 16; o > 0; o >>= 1)
                m = fmaxf(m, __shfl_xor_sync(0xffffffffu, m, o));
            float s = 0.f;
#pragma unroll
            for (int j = 0; j < 16; j++) {
                v[j] = __expf(v[j] - m);
                s += v[j];
            }
#pragma unroll
            for (int o = 16; o > 0; o >>= 1)
                s += __shfl_xor_sync(0xffffffffu, s, o);
            float inv = 1.0f / s;
            __syncwarp();
#pragma unroll
            for (int j = 0; j < 8; j++)
                ((unsigned*)&Ss[row][0])[lane + 32 * j] =
                    packh2(v[2 * j] * inv, v[2 * j + 1] * inv);
        }
    }
    CP_WAIT0();
    __syncthreads();

    // Phase 3: O = P V
    {
        const int wm0 = (warp >> 2) * 16, wn0 = (warp & 3) * 16;
        float acc[2][4] = {};
        for (int ci = 0; ci < 8; ci++) {
            const int nt = ci * 64;
            const bool has_next = (ci < 7);
            if (has_next) { fill_kv((ci + 1) & 1, Vp, nt + 64); CP_COMMIT(); }

            const unsigned vb = kvsm + (unsigned)((ci & 1) * 9216);
#pragma unroll
            for (int ks = 0; ks < 4; ks++) {
                const int c = 16 * ks;
                unsigned af[4];
                const unsigned* P0 = (const unsigned*)&Ss[wm0 + g][0];
                const unsigned* P1 = (const unsigned*)&Ss[wm0 + g + 8][0];
                af[0] = P0[nt / 2 + 8 * ks + tg];
                af[1] = P1[nt / 2 + 8 * ks + tg];
                af[2] = P0[nt / 2 + 8 * ks + tg + 4];
                af[3] = P1[nt / 2 + 8 * ks + tg + 4];
#pragma unroll
                for (int ni = 0; ni < 2; ni++) {
                    int dbase = wn0 + ni * 8;
                    unsigned addr = vb + (unsigned)((c + (lane & 15)) * 144 + dbase * 2);
                    unsigned bf[2];
                    ldmx2t(bf[0], bf[1], addr);
                    mma_f16(acc[ni], af, bf);
                }
            }
            if (has_next) {
                CP_WAIT0();
                __syncthreads();
            }
        }

#pragma unroll
        for (int ni = 0; ni < 2; ni++) {
            int qg = mt + wm0 + g;
            int d = wn0 + ni * 8 + 2 * tg;
            unsigned* yp = (unsigned*)g_Y;
            yp[((size_t)(b * T_ + qg) * C_ + h * DH_ + d) >> 1] =
                packh2(acc[ni][0], acc[ni][1]);
            yp[((size_t)(b * T_ + qg + 8) * C_ + h * DH_ + d) >> 1] =
                packh2(acc[ni][2], acc[ni][3]);
        }
    }
}

// ---------------------------------------------------------------------------
extern "C" void kernel_launch(void* const* d_in, const int* in_sizes, int n_in,
                              void* d_out, int out_size)
{
    const float* x    = (const float*)d_in[0];
    const float* src  = (const float*)d_in[1];
    const float* fmap = (const float*)d_in[2];
    const float* bmap = (const float*)d_in[3];
    const float* Wq   = (const float*)d_in[4];
    const float* bq   = (const float*)d_in[5];
    const float* Wk   = (const float*)d_in[6];
    const float* bk   = (const float*)d_in[7];
    const float* Wv   = (const float*)d_in[8];
    const float* bv   = (const float*)d_in[9];
    const float* Wp   = (const float*)d_in[10];
    const float* bp   = (const float*)d_in[11];
    float* out = (float*)d_out;

    cudaFuncSetAttribute(gemm_qkv, cudaFuncAttributeMaxDynamicSharedMemorySize,
                         GEMM_SMEM);
    cudaFuncSetAttribute(gemm_out, cudaFuncAttributeMaxDynamicSharedMemorySize,
                         GEMM_SMEM);
    cudaFuncSetAttribute(attn_fused, cudaFuncAttributeMaxDynamicSharedMemorySize,
                         ATTN_SMEM);

    prep_fp16<<<12288, 256>>>((const float4*)x, (const float4*)src,
                              (const float4*)Wq, (const float4*)Wk,
                              (const float4*)Wv, (const float4*)Wp);
    prep_mask<<<dim3(HW_ / 32, HW_ / 32, B_), 256>>>(fmap, bmap);

    const int M = B_ * T_;                  // 4096
    dim3 gQKV(C_ / 128, M / 128, 3);        // 8 x 32 x 3
    gemm_qkv<<<gQKV, 256, GEMM_SMEM>>>(bq, bk, bv);

    dim3 gAttn(T_ / 32, B_ * NH_);          // 16 x 128
    attn_fused<<<gAttn, 256, ATTN_SMEM>>>();

    dim3 gProj(C_ / 128, M / 128);          // 8 x 32
    gemm_out<<<gProj, 256, GEMM_SMEM>>>(bp, out);
}